// round 16
// baseline (speedup 1.0000x reference)
#include <cuda_runtime.h>
#include <cuda_fp16.h>
#include <cstdint>

// ---------------------------------------------------------------------------
// GPT block, fp16 mma.sync (m16n8k16, fp32 accum).
// R16 = R15 (888.9 us) + proj GEMM converted to split-K=4 (red.add epilogue,
// kills its 1.73->2.0 wave quantization). out pre-initialized with x+b_proj
// inside the head kernel's LN1 branch (x already loaded there).
// ---------------------------------------------------------------------------

#define D_MODEL 1024
#define T_SEQ   2048
#define N_BATCH 4
#define ROWS    (N_BATCH * T_SEQ)   // 8192

__device__ __half g_h16[ROWS * D_MODEL];
__device__ __half g_w16[12582912];
__device__ __half g_qkv16[(size_t)ROWS * 3 * D_MODEL];
__device__ __half g_p16[(size_t)N_BATCH * T_SEQ * T_SEQ];
__device__ __half g_y16[ROWS * D_MODEL];
__device__ __half g_mlp16[(size_t)ROWS * 4 * D_MODEL];
__device__ float  g_rowsum[ROWS];

#define OFF_PROJ 3145728
#define OFF_FC   4194304
#define OFF_FC2  8388608

__device__ __forceinline__ uint32_t smem_u32(const void* p) {
    uint32_t a;
    asm("{ .reg .u64 t; cvta.to.shared.u64 t, %1; cvt.u32.u64 %0, t; }" : "=r"(a) : "l"(p));
    return a;
}
__device__ __forceinline__ void cp_async16(uint32_t dst, const void* src) {
    asm volatile("cp.async.cg.shared.global [%0], [%1], 16;" :: "r"(dst), "l"(src));
}
#define CP_COMMIT() asm volatile("cp.async.commit_group;" ::: "memory")
#define CP_WAIT1()  asm volatile("cp.async.wait_group 1;" ::: "memory")

__device__ __forceinline__ void ldsm4(uint32_t& r0, uint32_t& r1, uint32_t& r2,
                                      uint32_t& r3, uint32_t addr) {
    asm volatile("ldmatrix.sync.aligned.m8n8.x4.shared.b16 {%0,%1,%2,%3}, [%4];"
                 : "=r"(r0), "=r"(r1), "=r"(r2), "=r"(r3) : "r"(addr));
}
__device__ __forceinline__ void ldsm4t(uint32_t& r0, uint32_t& r1, uint32_t& r2,
                                       uint32_t& r3, uint32_t addr) {
    asm volatile("ldmatrix.sync.aligned.m8n8.x4.trans.shared.b16 {%0,%1,%2,%3}, [%4];"
                 : "=r"(r0), "=r"(r1), "=r"(r2), "=r"(r3) : "r"(addr));
}
__device__ __forceinline__ void mma16816(float* c, const uint32_t* a, const uint32_t* b) {
    asm volatile(
        "mma.sync.aligned.m16n8k16.row.col.f32.f16.f16.f32 "
        "{%0,%1,%2,%3},{%4,%5,%6,%7},{%8,%9},{%0,%1,%2,%3};"
        : "+f"(c[0]), "+f"(c[1]), "+f"(c[2]), "+f"(c[3])
        : "r"(a[0]), "r"(a[1]), "r"(a[2]), "r"(a[3]), "r"(b[0]), "r"(b[1]));
}
__device__ __forceinline__ void redadd(float* p, float v) {
    asm volatile("red.global.add.f32 [%0], %1;" :: "l"(p), "f"(v) : "memory");
}
__device__ __forceinline__ float gelu_f(float x) {
    float u = 0.7978845608028654f * (x + 0.044715f * x * x * x);
    return x / (1.0f + __expf(-2.0f * u));
}

// ---------------------------------------------------------------------------
// CTA 128x128x64 (BK=64), 256 thr, 8 warps 2(M)x4(N) of 64x32, 3-stage
// cp.async, 2 CTA/SM. (Frozen mainloop.)
// CAUSAL: 0 none; 1 triangular grid; 2 K truncated at diagonal (M reversed).
// EPI: 0 none, 1 +bias, 2 +bias+Res, 3 gelu(x+bias), 4 red.add into fp32 C,
//      5 exp(v/8)+causal mask+rowsum red.add into Res (QK^T),
//      6 divide by rowsum in bias[] (AV).
// OUTH: 1 fp16 C, 0 fp32 C.   TRB: B stored [K,N] row-major (ldmatrix.trans).
// ---------------------------------------------------------------------------
template<int CAUSAL, int EPI, int OUTH, int TRB>
__global__ __launch_bounds__(256, 2)
void hgemm(const __half* __restrict__ A, const __half* __restrict__ B,
           const float* __restrict__ bias, const float* __restrict__ Res,
           void* __restrict__ Cv, int K, int lda, int ldb, int ldc,
           long long sA, long long sB, long long sC)
{
    extern __shared__ char smem[];
    constexpr int A_SZ = 128 * 144;
    constexpr int B_SZ = TRB ? 64 * 272 : 128 * 144;
    constexpr int STG  = A_SZ + B_SZ;

    int bm0, bn0;
    if (CAUSAL == 1) {
        const int xb = blockIdx.x;
        int mt = (int)((sqrtf(8.0f * xb + 1.0f) - 1.0f) * 0.5f);
        while ((mt + 1) * (mt + 2) / 2 <= xb) mt++;
        while (mt * (mt + 1) / 2 > xb) mt--;
        const int nt = xb - mt * (mt + 1) / 2;
        bm0 = mt * 128; bn0 = nt * 128;
    } else if (CAUSAL == 2) {
        bm0 = ((int)gridDim.y - 1 - (int)blockIdx.y) * 128;
        bn0 = blockIdx.x * 128;
    } else {
        bm0 = blockIdx.y * 128;
        bn0 = blockIdx.x * 128;
    }

    A += blockIdx.z * sA;
    B += blockIdx.z * sB;

    const int tid = threadIdx.x, lane = tid & 31, wid = tid >> 5;
    const int wm = (wid >> 2) * 64, wn = (wid & 3) * 32;
    const uint32_t sb0 = smem_u32(smem);

    int KT = K >> 6;
    if (CAUSAL == 2) { int lim = (bm0 + 128) >> 6; if (lim < KT) KT = lim; }

    float acc[4][4][4] = {};

    auto issue = [&](int buf, int kt) {
        const __half* Ag = A + (long long)bm0 * lda + kt * 64;
        const uint32_t sa = sb0 + buf * STG, sbB = sa + A_SZ;
        #pragma unroll
        for (int i = 0; i < 4; i++) {
            const int id = tid + i * 256;
            const int row = id >> 3, ch = id & 7;
            cp_async16(sa + row * 144 + ch * 16, Ag + (long long)row * lda + ch * 8);
        }
        if (TRB) {
            const __half* Bg = B + (long long)(kt * 64) * ldb + bn0;
            #pragma unroll
            for (int i = 0; i < 4; i++) {
                const int id = tid + i * 256;
                const int row = id >> 4, c = id & 15;
                cp_async16(sbB + row * 272 + c * 16, Bg + (long long)row * ldb + c * 8);
            }
        } else {
            const __half* Bg = B + (long long)bn0 * ldb + kt * 64;
            #pragma unroll
            for (int i = 0; i < 4; i++) {
                const int id = tid + i * 256;
                const int row = id >> 3, ch = id & 7;
                cp_async16(sbB + row * 144 + ch * 16, Bg + (long long)row * ldb + ch * 8);
            }
        }
    };

    issue(0, 0); CP_COMMIT();
    issue(1, 1); CP_COMMIT();

    const int rlow = lane & 15;
    const int chq  = lane >> 4;

    for (int kt = 0; kt < KT; ++kt) {
        CP_WAIT1();
        __syncthreads();
        const int buf = kt - (kt / 3) * 3;
        const uint32_t sa = sb0 + buf * STG, sbB = sa + A_SZ;
        #pragma unroll
        for (int ks = 0; ks < 4; ks++) {
            uint32_t af[4][4], bf[2][4];
            #pragma unroll
            for (int mi = 0; mi < 4; mi++)
                ldsm4(af[mi][0], af[mi][1], af[mi][2], af[mi][3],
                      sa + (wm + mi * 16 + rlow) * 144 + (ks * 2 + chq) * 16);
            #pragma unroll
            for (int nj = 0; nj < 2; nj++) {
                if (TRB)
                    ldsm4t(bf[nj][0], bf[nj][1], bf[nj][2], bf[nj][3],
                           sbB + (ks * 16 + rlow) * 272 + (wn + nj * 16 + chq * 8) * 2);
                else
                    ldsm4(bf[nj][0], bf[nj][1], bf[nj][2], bf[nj][3],
                          sbB + (wn + nj * 16 + rlow) * 144 + (ks * 2 + chq) * 16);
            }
            #pragma unroll
            for (int mi = 0; mi < 4; mi++)
                #pragma unroll
                for (int ni = 0; ni < 4; ni++) {
                    uint32_t bb[2];
                    if (TRB) {
                        bb[0] = bf[ni >> 1][(ni & 1) * 2];
                        bb[1] = bf[ni >> 1][(ni & 1) * 2 + 1];
                    } else {
                        bb[0] = bf[ni >> 1][ni & 1];
                        bb[1] = bf[ni >> 1][2 + (ni & 1)];
                    }
                    mma16816(acc[mi][ni], af[mi], bb);
                }
        }
        const int nf = kt + 2;
        if (nf < KT) issue(nf - (nf / 3) * 3, nf);
        CP_COMMIT();
    }

    // Epilogue
    const int g = lane >> 2, t2 = (lane & 3) * 2;
    #pragma unroll
    for (int mi = 0; mi < 4; mi++) {
        const long long m0 = bm0 + wm + mi * 16 + g;
        float rs0 = 0.0f, rs1 = 0.0f;        // EPI==5 rowsum partials
        float inv0 = 1.0f, inv8 = 1.0f;      // EPI==6 rowsum reciprocals
        if (EPI == 6) {
            inv0 = 1.0f / bias[(long long)blockIdx.z * T_SEQ + m0];
            inv8 = 1.0f / bias[(long long)blockIdx.z * T_SEQ + m0 + 8];
        }
        #pragma unroll
        for (int ni = 0; ni < 4; ni++) {
            const int n = bn0 + wn + ni * 8 + t2;
            float v0 = acc[mi][ni][0], v1 = acc[mi][ni][1];
            float v2 = acc[mi][ni][2], v3 = acc[mi][ni][3];
            if (EPI >= 1 && EPI <= 3) {
                const float b0 = bias[n], b1 = bias[n + 1];
                v0 += b0; v1 += b1; v2 += b0; v3 += b1;
            }
            if (EPI == 3) {
                v0 = gelu_f(v0); v1 = gelu_f(v1); v2 = gelu_f(v2); v3 = gelu_f(v3);
            }
            if (EPI == 2) {
                v0 += Res[m0 * ldc + n];       v1 += Res[m0 * ldc + n + 1];
                v2 += Res[(m0 + 8) * ldc + n]; v3 += Res[(m0 + 8) * ldc + n + 1];
            }
            if (EPI == 5) {
                v0 = (n     <= m0)     ? __expf(v0 * 0.125f) : 0.0f;
                v1 = (n + 1 <= m0)     ? __expf(v1 * 0.125f) : 0.0f;
                v2 = (n     <= m0 + 8) ? __expf(v2 * 0.125f) : 0.0f;
                v3 = (n + 1 <= m0 + 8) ? __expf(v3 * 0.125f) : 0.0f;
                rs0 += v0 + v1;
                rs1 += v2 + v3;
            }
            if (EPI == 6) {
                v0 *= inv0; v1 *= inv0; v2 *= inv8; v3 *= inv8;
            }
            if (EPI == 4) {
                float* C = (float*)Cv;
                redadd(&C[m0 * ldc + n], v0);       redadd(&C[m0 * ldc + n + 1], v1);
                redadd(&C[(m0 + 8) * ldc + n], v2); redadd(&C[(m0 + 8) * ldc + n + 1], v3);
            } else if (OUTH) {
                __half* C = (__half*)Cv + blockIdx.z * sC;
                *(__half2*)(C + m0 * ldc + n)       = __floats2half2_rn(v0, v1);
                *(__half2*)(C + (m0 + 8) * ldc + n) = __floats2half2_rn(v2, v3);
            } else {
                float* C = (float*)Cv + blockIdx.z * sC;
                *(float2*)(C + m0 * ldc + n)       = make_float2(v0, v1);
                *(float2*)(C + (m0 + 8) * ldc + n) = make_float2(v2, v3);
            }
        }
        if (EPI == 5) {
            rs0 += __shfl_xor_sync(0xffffffffu, rs0, 1);
            rs0 += __shfl_xor_sync(0xffffffffu, rs0, 2);
            rs1 += __shfl_xor_sync(0xffffffffu, rs1, 1);
            rs1 += __shfl_xor_sync(0xffffffffu, rs1, 2);
            if ((lane & 3) == 0) {
                float* RS = const_cast<float*>(Res);
                redadd(&RS[(long long)blockIdx.z * T_SEQ + m0], rs0);
                redadd(&RS[(long long)blockIdx.z * T_SEQ + m0 + 8], rs1);
            }
        }
    }
}

// ---------------------------------------------------------------------------
// MERGED head kernel: [0,6144) weight transpose; [6144,14336) LN1 (also
// pre-initializes out = x + b_proj for the split-K proj); [14336,14344)
// zero the rowsum array.
// ---------------------------------------------------------------------------
__global__ __launch_bounds__(256)
void head_kernel(const float* __restrict__ wa, const float* __restrict__ wp,
                 const float* __restrict__ wf, const float* __restrict__ wf2,
                 __half* __restrict__ wout,
                 const float* __restrict__ x, const float* __restrict__ g1,
                 const float* __restrict__ b1, __half* __restrict__ h16,
                 float* __restrict__ rowsum,
                 float* __restrict__ outbuf, const float* __restrict__ bproj)
{
    __shared__ float s[32 * 67];
    const int tid = threadIdx.x;

    if (blockIdx.x >= 14336) {
        const int idx = (blockIdx.x - 14336) * 256 + tid;   // 2048 threads
        reinterpret_cast<float4*>(rowsum)[idx] = make_float4(0.f, 0.f, 0.f, 0.f);
        return;
    }
    if (blockIdx.x < 6144) {
        int id = blockIdx.x;
        const float* in; __half* o; int ldi, ldo, bx, by;
        if (id < 1536)      { in = wa;  o = wout;            ldi = 3072; ldo = 1024; bx = id % 48; by = id / 48; }
        else if (id < 2048) { id -= 1536; in = wp;  o = wout + OFF_PROJ; ldi = 1024; ldo = 1024; bx = id % 16; by = id / 16; }
        else if (id < 4096) { id -= 2048; in = wf;  o = wout + OFF_FC;   ldi = 4096; ldo = 1024; bx = id % 64; by = id / 64; }
        else                { id -= 4096; in = wf2; o = wout + OFF_FC2;  ldi = 1024; ldo = 4096; bx = id % 16; by = id / 16; }
        const int r0 = by * 32, c0 = bx * 64;

        #pragma unroll
        for (int i = 0; i < 2; i++) {
            const int idx = tid + i * 256;
            const int row = idx >> 4, c4 = (idx & 15) * 4;
            const float4 v = *reinterpret_cast<const float4*>(
                in + (long long)(r0 + row) * ldi + c0 + c4);
            s[row * 67 + c4 + 0] = v.x;
            s[row * 67 + c4 + 1] = v.y;
            s[row * 67 + c4 + 2] = v.z;
            s[row * 67 + c4 + 3] = v.w;
        }
        __syncthreads();

        const int oc = tid >> 2;
        const int ch = (tid & 3) * 8;
        uint32_t u[4];
        #pragma unroll
        for (int j = 0; j < 4; j++) {
            __half2 h = __floats2half2_rn(s[(ch + 2 * j) * 67 + oc],
                                          s[(ch + 2 * j + 1) * 67 + oc]);
            u[j] = *reinterpret_cast<uint32_t*>(&h);
        }
        *reinterpret_cast<uint4*>(o + (long long)(c0 + oc) * ldo + r0 + ch) =
            make_uint4(u[0], u[1], u[2], u[3]);
    } else {
        const size_t row = blockIdx.x - 6144;
        float* rs = s;
        float* rq = s + 8;
        const float4 v = reinterpret_cast<const float4*>(x + row * D_MODEL)[tid];
        float sm  = v.x + v.y + v.z + v.w;
        float sq  = v.x * v.x + v.y * v.y + v.z * v.z + v.w * v.w;
        #pragma unroll
        for (int o = 16; o; o >>= 1) {
            sm += __shfl_xor_sync(0xffffffffu, sm, o);
            sq += __shfl_xor_sync(0xffffffffu, sq, o);
        }
        if ((tid & 31) == 0) { rs[tid >> 5] = sm; rq[tid >> 5] = sq; }

        // pre-init out = x + b_proj while the reduction lands
        const float4 bp = reinterpret_cast<const float4*>(bproj)[tid];
        float4 w = v;
        w.x += bp.x; w.y += bp.y; w.z += bp.z; w.w += bp.w;
        reinterpret_cast<float4*>(outbuf + row * D_MODEL)[tid] = w;

        __syncthreads();
        float st = 0.0f, qt = 0.0f;
        #pragma unroll
        for (int i = 0; i < 8; i++) { st += rs[i]; qt += rq[i]; }
        const float mean = st * (1.0f / D_MODEL);
        const float var  = qt * (1.0f / D_MODEL) - mean * mean;
        const float rstd = rsqrtf(var + 1e-5f);

        const float4 gv = reinterpret_cast<const float4*>(g1)[tid];
        const float4 bv = reinterpret_cast<const float4*>(b1)[tid];
        const float o0 = (v.x - mean) * rstd * gv.x + bv.x;
        const float o1 = (v.y - mean) * rstd * gv.y + bv.y;
        const float o2 = (v.z - mean) * rstd * gv.z + bv.z;
        const float o3 = (v.w - mean) * rstd * gv.w + bv.w;
        __half2* op = reinterpret_cast<__half2*>(h16 + row * D_MODEL);
        op[2 * tid]     = __floats2half2_rn(o0, o1);
        op[2 * tid + 1] = __floats2half2_rn(o2, o3);
    }
}

// -------- LayerNorm -> fp16, optionally also out += bias2 (fused) --------
template<int ADDB>
__global__ __launch_bounds__(256)
void ln_kernel(const float* __restrict__ x, const float* __restrict__ g,
               const float* __restrict__ b, __half* __restrict__ out,
               float* __restrict__ xio, const float* __restrict__ bias2)
{
    const size_t row = blockIdx.x;
    const float4 v = reinterpret_cast<const float4*>(x + row * D_MODEL)[threadIdx.x];
    float s  = v.x + v.y + v.z + v.w;
    float sq = v.x * v.x + v.y * v.y + v.z * v.z + v.w * v.w;

    __shared__ float rs[8], rq[8];
    #pragma unroll
    for (int o = 16; o; o >>= 1) {
        s  += __shfl_xor_sync(0xffffffffu, s, o);
        sq += __shfl_xor_sync(0xffffffffu, sq, o);
    }
    if ((threadIdx.x & 31) == 0) { rs[threadIdx.x >> 5] = s; rq[threadIdx.x >> 5] = sq; }
    __syncthreads();
    float st = 0.0f, qt = 0.0f;
    #pragma unroll
    for (int i = 0; i < 8; i++) { st += rs[i]; qt += rq[i]; }
    const float mean = st * (1.0f / D_MODEL);
    const float var  = qt * (1.0f / D_MODEL) - mean * mean;
    const float rstd = rsqrtf(var + 1e-5f);

    const float4 gv = reinterpret_cast<const float4*>(g)[threadIdx.x];
    const float4 bv = reinterpret_cast<const float4*>(b)[threadIdx.x];
    const float o0 = (v.x - mean) * rstd * gv.x + bv.x;
    const float o1 = (v.y - mean) * rstd * gv.y + bv.y;
    const float o2 = (v.z - mean) * rstd * gv.z + bv.z;
    const float o3 = (v.w - mean) * rstd * gv.w + bv.w;
    __half2* op = reinterpret_cast<__half2*>(out + row * D_MODEL);
    op[2 * threadIdx.x]     = __floats2half2_rn(o0, o1);
    op[2 * threadIdx.x + 1] = __floats2half2_rn(o2, o3);
    if (ADDB) {
        const float4 b2 = reinterpret_cast<const float4*>(bias2)[threadIdx.x];
        float4 w = v;
        w.x += b2.x; w.y += b2.y; w.z += b2.z; w.w += b2.w;
        reinterpret_cast<float4*>(xio + row * D_MODEL)[threadIdx.x] = w;
    }
}

// ---------------------------------------------------------------------------
extern "C" void kernel_launch(void* const* d_in, const int* in_sizes, int n_in,
                              void* d_out, int out_size)
{
    const float* x      = (const float*)d_in[0];
    const float* w_attn = (const float*)d_in[1];
    const float* b_attn = (const float*)d_in[2];
    const float* w_proj = (const float*)d_in[3];
    const float* b_proj = (const float*)d_in[4];
    const float* ln1_g  = (const float*)d_in[5];
    const float* ln1_b  = (const float*)d_in[6];
    const float* ln2_g  = (const float*)d_in[7];
    const float* ln2_b  = (const float*)d_in[8];
    const float* w_fc   = (const float*)d_in[9];
    const float* b_fc   = (const float*)d_in[10];
    const float* w_fc2  = (const float*)d_in[11];
    const float* b_fc2  = (const float*)d_in[12];
    float* out = (float*)d_out;

    __half *h16, *w16, *qkv16, *p16, *y16, *mlp16;
    float  *rsum;
    cudaGetSymbolAddress((void**)&h16,   g_h16);
    cudaGetSymbolAddress((void**)&w16,   g_w16);
    cudaGetSymbolAddress((void**)&qkv16, g_qkv16);
    cudaGetSymbolAddress((void**)&p16,   g_p16);
    cudaGetSymbolAddress((void**)&y16,   g_y16);
    cudaGetSymbolAddress((void**)&mlp16, g_mlp16);
    cudaGetSymbolAddress((void**)&rsum,  g_rowsum);

    const int SM_NT  = 3 * (128 * 144 + 128 * 144);   // 110592
    const int SM_TRB = 3 * (128 * 144 + 64 * 272);    // 107520
    cudaFuncSetAttribute(hgemm<0,1,1,0>, cudaFuncAttributeMaxDynamicSharedMemorySize, SM_NT);
    cudaFuncSetAttribute(hgemm<1,5,1,0>, cudaFuncAttributeMaxDynamicSharedMemorySize, SM_NT);
    cudaFuncSetAttribute(hgemm<2,6,1,1>, cudaFuncAttributeMaxDynamicSharedMemorySize, SM_TRB);
    cudaFuncSetAttribute(hgemm<0,3,1,0>, cudaFuncAttributeMaxDynamicSharedMemorySize, SM_NT);
    cudaFuncSetAttribute(hgemm<0,4,0,0>, cudaFuncAttributeMaxDynamicSharedMemorySize, SM_NT);

    const long long sQ = (long long)T_SEQ * 3 * D_MODEL;
    const long long sS = (long long)T_SEQ * T_SEQ;
    const long long sY = (long long)T_SEQ * D_MODEL;

    // 0+1) weight transposes, LN1 (+ out = x + b_proj), rowsum zero-init
    head_kernel<<<6144 + ROWS + 8, 256>>>(w_attn, w_proj, w_fc, w_fc2, w16,
                                          x, ln1_g, ln1_b, h16, rsum,
                                          out, b_proj);

    // 2) qkv = h @ w_attn + b_attn  (fp16 out)
    hgemm<0,1,1,0><<<dim3(24, 64, 1), 256, SM_NT>>>(
        h16, w16, b_attn, nullptr, qkv16, 1024, 1024, 1024, 3072, 0, 0, 0);

    // 3) expL = exp(q @ k^T / 8), causal-masked, rowsums accumulated
    hgemm<1,5,1,0><<<dim3(136, 1, N_BATCH), 256, SM_NT>>>(
        qkv16, qkv16 + D_MODEL, nullptr, rsum, p16,
        1024, 3072, 3072, 2048, sQ, sQ, sS);

    // 4) y = (expL @ v) / rowsum  (TRANS-B; K truncated at diagonal)
    hgemm<2,6,1,1><<<dim3(8, 16, N_BATCH), 256, SM_TRB>>>(
        p16, qkv16 + 2 * D_MODEL, rsum, nullptr, y16,
        2048, 2048, 3072, 1024, sS, sQ, sY);

    // 5) out += y @ w_proj, split-K=4 (out pre-init = x + b_proj)
    hgemm<0,4,0,0><<<dim3(8, 64, 4), 256, SM_NT>>>(
        y16, w16 + OFF_PROJ, nullptr, nullptr, out,
        256, 1024, 1024, 1024, 256, 256, 0);

    // 6) LN2 -> h16, fused with out += b_fc2 (pre-add for split-K fc2)
    ln_kernel<1><<<ROWS, 256>>>(out, ln2_g, ln2_b, h16, out, b_fc2);

    // 7) mlp = gelu(h @ w_fc + b_fc)  (fp16 out)
    hgemm<0,3,1,0><<<dim3(32, 64, 1), 256, SM_NT>>>(
        h16, w16 + OFF_FC, b_fc, nullptr, mlp16, 1024, 1024, 1024, 4096, 0, 0, 0);

    // 8) out += mlp @ w_fc2, split-K=4 via red.global.add.f32
    hgemm<0,4,0,0><<<dim3(8, 64, 4), 256, SM_NT>>>(
        mlp16, w16 + OFF_FC2, nullptr, nullptr, out,
        1024, 4096, 4096, 1024, 1024, 1024, 0);
}

// round 17
// speedup vs baseline: 1.0181x; 1.0181x over previous
#include <cuda_runtime.h>
#include <cuda_fp16.h>
#include <cstdint>

// ---------------------------------------------------------------------------
// GPT block, fp16 mma.sync (m16n8k16, fp32 accum).
// R17 = R15 (888.9 us, verified optimum; R16's proj split-K reverted — its
// atomic traffic cost more than the wave-quantization it saved) + fc2 bias
// folded into the split-K epilogue's z==0 slice (deletes a 32MB out rewrite
// from the LN2 kernel).
// ---------------------------------------------------------------------------

#define D_MODEL 1024
#define T_SEQ   2048
#define N_BATCH 4
#define ROWS    (N_BATCH * T_SEQ)   // 8192

__device__ __half g_h16[ROWS * D_MODEL];
__device__ __half g_w16[12582912];
__device__ __half g_qkv16[(size_t)ROWS * 3 * D_MODEL];
__device__ __half g_p16[(size_t)N_BATCH * T_SEQ * T_SEQ];
__device__ __half g_y16[ROWS * D_MODEL];
__device__ __half g_mlp16[(size_t)ROWS * 4 * D_MODEL];
__device__ float  g_rowsum[ROWS];

#define OFF_PROJ 3145728
#define OFF_FC   4194304
#define OFF_FC2  8388608

__device__ __forceinline__ uint32_t smem_u32(const void* p) {
    uint32_t a;
    asm("{ .reg .u64 t; cvta.to.shared.u64 t, %1; cvt.u32.u64 %0, t; }" : "=r"(a) : "l"(p));
    return a;
}
__device__ __forceinline__ void cp_async16(uint32_t dst, const void* src) {
    asm volatile("cp.async.cg.shared.global [%0], [%1], 16;" :: "r"(dst), "l"(src));
}
#define CP_COMMIT() asm volatile("cp.async.commit_group;" ::: "memory")
#define CP_WAIT1()  asm volatile("cp.async.wait_group 1;" ::: "memory")

__device__ __forceinline__ void ldsm4(uint32_t& r0, uint32_t& r1, uint32_t& r2,
                                      uint32_t& r3, uint32_t addr) {
    asm volatile("ldmatrix.sync.aligned.m8n8.x4.shared.b16 {%0,%1,%2,%3}, [%4];"
                 : "=r"(r0), "=r"(r1), "=r"(r2), "=r"(r3) : "r"(addr));
}
__device__ __forceinline__ void ldsm4t(uint32_t& r0, uint32_t& r1, uint32_t& r2,
                                       uint32_t& r3, uint32_t addr) {
    asm volatile("ldmatrix.sync.aligned.m8n8.x4.trans.shared.b16 {%0,%1,%2,%3}, [%4];"
                 : "=r"(r0), "=r"(r1), "=r"(r2), "=r"(r3) : "r"(addr));
}
__device__ __forceinline__ void mma16816(float* c, const uint32_t* a, const uint32_t* b) {
    asm volatile(
        "mma.sync.aligned.m16n8k16.row.col.f32.f16.f16.f32 "
        "{%0,%1,%2,%3},{%4,%5,%6,%7},{%8,%9},{%0,%1,%2,%3};"
        : "+f"(c[0]), "+f"(c[1]), "+f"(c[2]), "+f"(c[3])
        : "r"(a[0]), "r"(a[1]), "r"(a[2]), "r"(a[3]), "r"(b[0]), "r"(b[1]));
}
__device__ __forceinline__ void redadd(float* p, float v) {
    asm volatile("red.global.add.f32 [%0], %1;" :: "l"(p), "f"(v) : "memory");
}
__device__ __forceinline__ float gelu_f(float x) {
    float u = 0.7978845608028654f * (x + 0.044715f * x * x * x);
    return x / (1.0f + __expf(-2.0f * u));
}

// ---------------------------------------------------------------------------
// CTA 128x128x64 (BK=64), 256 thr, 8 warps 2(M)x4(N) of 64x32, 3-stage
// cp.async, 2 CTA/SM. (Frozen mainloop.)
// CAUSAL: 0 none; 1 triangular grid; 2 K truncated at diagonal (M reversed).
// EPI: 0 none, 1 +bias, 2 +bias+Res, 3 gelu(x+bias), 4 red.add into fp32 C,
//      5 exp(v/8)+causal mask+rowsum red.add into Res (QK^T),
//      6 divide by rowsum in bias[] (AV),
//      7 red.add into fp32 C, +bias on the z==0 split only (split-K fc2).
// OUTH: 1 fp16 C, 0 fp32 C.   TRB: B stored [K,N] row-major (ldmatrix.trans).
// ---------------------------------------------------------------------------
template<int CAUSAL, int EPI, int OUTH, int TRB>
__global__ __launch_bounds__(256, 2)
void hgemm(const __half* __restrict__ A, const __half* __restrict__ B,
           const float* __restrict__ bias, const float* __restrict__ Res,
           void* __restrict__ Cv, int K, int lda, int ldb, int ldc,
           long long sA, long long sB, long long sC)
{
    extern __shared__ char smem[];
    constexpr int A_SZ = 128 * 144;
    constexpr int B_SZ = TRB ? 64 * 272 : 128 * 144;
    constexpr int STG  = A_SZ + B_SZ;

    int bm0, bn0;
    if (CAUSAL == 1) {
        const int xb = blockIdx.x;
        int mt = (int)((sqrtf(8.0f * xb + 1.0f) - 1.0f) * 0.5f);
        while ((mt + 1) * (mt + 2) / 2 <= xb) mt++;
        while (mt * (mt + 1) / 2 > xb) mt--;
        const int nt = xb - mt * (mt + 1) / 2;
        bm0 = mt * 128; bn0 = nt * 128;
    } else if (CAUSAL == 2) {
        bm0 = ((int)gridDim.y - 1 - (int)blockIdx.y) * 128;
        bn0 = blockIdx.x * 128;
    } else {
        bm0 = blockIdx.y * 128;
        bn0 = blockIdx.x * 128;
    }

    A += blockIdx.z * sA;
    B += blockIdx.z * sB;

    const int tid = threadIdx.x, lane = tid & 31, wid = tid >> 5;
    const int wm = (wid >> 2) * 64, wn = (wid & 3) * 32;
    const uint32_t sb0 = smem_u32(smem);

    int KT = K >> 6;
    if (CAUSAL == 2) { int lim = (bm0 + 128) >> 6; if (lim < KT) KT = lim; }

    float acc[4][4][4] = {};

    auto issue = [&](int buf, int kt) {
        const __half* Ag = A + (long long)bm0 * lda + kt * 64;
        const uint32_t sa = sb0 + buf * STG, sbB = sa + A_SZ;
        #pragma unroll
        for (int i = 0; i < 4; i++) {
            const int id = tid + i * 256;
            const int row = id >> 3, ch = id & 7;
            cp_async16(sa + row * 144 + ch * 16, Ag + (long long)row * lda + ch * 8);
        }
        if (TRB) {
            const __half* Bg = B + (long long)(kt * 64) * ldb + bn0;
            #pragma unroll
            for (int i = 0; i < 4; i++) {
                const int id = tid + i * 256;
                const int row = id >> 4, c = id & 15;
                cp_async16(sbB + row * 272 + c * 16, Bg + (long long)row * ldb + c * 8);
            }
        } else {
            const __half* Bg = B + (long long)bn0 * ldb + kt * 64;
            #pragma unroll
            for (int i = 0; i < 4; i++) {
                const int id = tid + i * 256;
                const int row = id >> 3, ch = id & 7;
                cp_async16(sbB + row * 144 + ch * 16, Bg + (long long)row * ldb + ch * 8);
            }
        }
    };

    issue(0, 0); CP_COMMIT();
    issue(1, 1); CP_COMMIT();

    const int rlow = lane & 15;
    const int chq  = lane >> 4;

    for (int kt = 0; kt < KT; ++kt) {
        CP_WAIT1();
        __syncthreads();
        const int buf = kt - (kt / 3) * 3;
        const uint32_t sa = sb0 + buf * STG, sbB = sa + A_SZ;
        #pragma unroll
        for (int ks = 0; ks < 4; ks++) {
            uint32_t af[4][4], bf[2][4];
            #pragma unroll
            for (int mi = 0; mi < 4; mi++)
                ldsm4(af[mi][0], af[mi][1], af[mi][2], af[mi][3],
                      sa + (wm + mi * 16 + rlow) * 144 + (ks * 2 + chq) * 16);
            #pragma unroll
            for (int nj = 0; nj < 2; nj++) {
                if (TRB)
                    ldsm4t(bf[nj][0], bf[nj][1], bf[nj][2], bf[nj][3],
                           sbB + (ks * 16 + rlow) * 272 + (wn + nj * 16 + chq * 8) * 2);
                else
                    ldsm4(bf[nj][0], bf[nj][1], bf[nj][2], bf[nj][3],
                          sbB + (wn + nj * 16 + rlow) * 144 + (ks * 2 + chq) * 16);
            }
            #pragma unroll
            for (int mi = 0; mi < 4; mi++)
                #pragma unroll
                for (int ni = 0; ni < 4; ni++) {
                    uint32_t bb[2];
                    if (TRB) {
                        bb[0] = bf[ni >> 1][(ni & 1) * 2];
                        bb[1] = bf[ni >> 1][(ni & 1) * 2 + 1];
                    } else {
                        bb[0] = bf[ni >> 1][ni & 1];
                        bb[1] = bf[ni >> 1][2 + (ni & 1)];
                    }
                    mma16816(acc[mi][ni], af[mi], bb);
                }
        }
        const int nf = kt + 2;
        if (nf < KT) issue(nf - (nf / 3) * 3, nf);
        CP_COMMIT();
    }

    // Epilogue
    const int g = lane >> 2, t2 = (lane & 3) * 2;
    #pragma unroll
    for (int mi = 0; mi < 4; mi++) {
        const long long m0 = bm0 + wm + mi * 16 + g;
        float rs0 = 0.0f, rs1 = 0.0f;        // EPI==5 rowsum partials
        float inv0 = 1.0f, inv8 = 1.0f;      // EPI==6 rowsum reciprocals
        if (EPI == 6) {
            inv0 = 1.0f / bias[(long long)blockIdx.z * T_SEQ + m0];
            inv8 = 1.0f / bias[(long long)blockIdx.z * T_SEQ + m0 + 8];
        }
        #pragma unroll
        for (int ni = 0; ni < 4; ni++) {
            const int n = bn0 + wn + ni * 8 + t2;
            float v0 = acc[mi][ni][0], v1 = acc[mi][ni][1];
            float v2 = acc[mi][ni][2], v3 = acc[mi][ni][3];
            if (EPI >= 1 && EPI <= 3) {
                const float b0 = bias[n], b1 = bias[n + 1];
                v0 += b0; v1 += b1; v2 += b0; v3 += b1;
            }
            if (EPI == 3) {
                v0 = gelu_f(v0); v1 = gelu_f(v1); v2 = gelu_f(v2); v3 = gelu_f(v3);
            }
            if (EPI == 2) {
                v0 += Res[m0 * ldc + n];       v1 += Res[m0 * ldc + n + 1];
                v2 += Res[(m0 + 8) * ldc + n]; v3 += Res[(m0 + 8) * ldc + n + 1];
            }
            if (EPI == 5) {
                v0 = (n     <= m0)     ? __expf(v0 * 0.125f) : 0.0f;
                v1 = (n + 1 <= m0)     ? __expf(v1 * 0.125f) : 0.0f;
                v2 = (n     <= m0 + 8) ? __expf(v2 * 0.125f) : 0.0f;
                v3 = (n + 1 <= m0 + 8) ? __expf(v3 * 0.125f) : 0.0f;
                rs0 += v0 + v1;
                rs1 += v2 + v3;
            }
            if (EPI == 6) {
                v0 *= inv0; v1 *= inv0; v2 *= inv8; v3 *= inv8;
            }
            if (EPI == 7 && blockIdx.z == 0) {
                const float b0 = bias[n], b1 = bias[n + 1];
                v0 += b0; v1 += b1; v2 += b0; v3 += b1;
            }
            if (EPI == 4 || EPI == 7) {
                float* C = (float*)Cv;
                redadd(&C[m0 * ldc + n], v0);       redadd(&C[m0 * ldc + n + 1], v1);
                redadd(&C[(m0 + 8) * ldc + n], v2); redadd(&C[(m0 + 8) * ldc + n + 1], v3);
            } else if (OUTH) {
                __half* C = (__half*)Cv + blockIdx.z * sC;
                *(__half2*)(C + m0 * ldc + n)       = __floats2half2_rn(v0, v1);
                *(__half2*)(C + (m0 + 8) * ldc + n) = __floats2half2_rn(v2, v3);
            } else {
                float* C = (float*)Cv + blockIdx.z * sC;
                *(float2*)(C + m0 * ldc + n)       = make_float2(v0, v1);
                *(float2*)(C + (m0 + 8) * ldc + n) = make_float2(v2, v3);
            }
        }
        if (EPI == 5) {
            rs0 += __shfl_xor_sync(0xffffffffu, rs0, 1);
            rs0 += __shfl_xor_sync(0xffffffffu, rs0, 2);
            rs1 += __shfl_xor_sync(0xffffffffu, rs1, 1);
            rs1 += __shfl_xor_sync(0xffffffffu, rs1, 2);
            if ((lane & 3) == 0) {
                float* RS = const_cast<float*>(Res);
                redadd(&RS[(long long)blockIdx.z * T_SEQ + m0], rs0);
                redadd(&RS[(long long)blockIdx.z * T_SEQ + m0 + 8], rs1);
            }
        }
    }
}

// ---------------------------------------------------------------------------
// MERGED head kernel: [0,6144) weight transpose; [6144,14336) LN1;
// [14336,14344) zero the rowsum array.  (Exact R15 version.)
// ---------------------------------------------------------------------------
__global__ __launch_bounds__(256)
void head_kernel(const float* __restrict__ wa, const float* __restrict__ wp,
                 const float* __restrict__ wf, const float* __restrict__ wf2,
                 __half* __restrict__ wout,
                 const float* __restrict__ x, const float* __restrict__ g1,
                 const float* __restrict__ b1, __half* __restrict__ h16,
                 float* __restrict__ rowsum)
{
    __shared__ float s[32 * 67];
    const int tid = threadIdx.x;

    if (blockIdx.x >= 14336) {
        const int idx = (blockIdx.x - 14336) * 256 + tid;
        reinterpret_cast<float4*>(rowsum)[idx] = make_float4(0.f, 0.f, 0.f, 0.f);
        return;
    }
    if (blockIdx.x < 6144) {
        int id = blockIdx.x;
        const float* in; __half* o; int ldi, ldo, bx, by;
        if (id < 1536)      { in = wa;  o = wout;            ldi = 3072; ldo = 1024; bx = id % 48; by = id / 48; }
        else if (id < 2048) { id -= 1536; in = wp;  o = wout + OFF_PROJ; ldi = 1024; ldo = 1024; bx = id % 16; by = id / 16; }
        else if (id < 4096) { id -= 2048; in = wf;  o = wout + OFF_FC;   ldi = 4096; ldo = 1024; bx = id % 64; by = id / 64; }
        else                { id -= 4096; in = wf2; o = wout + OFF_FC2;  ldi = 1024; ldo = 4096; bx = id % 16; by = id / 16; }
        const int r0 = by * 32, c0 = bx * 64;

        #pragma unroll
        for (int i = 0; i < 2; i++) {
            const int idx = tid + i * 256;
            const int row = idx >> 4, c4 = (idx & 15) * 4;
            const float4 v = *reinterpret_cast<const float4*>(
                in + (long long)(r0 + row) * ldi + c0 + c4);
            s[row * 67 + c4 + 0] = v.x;
            s[row * 67 + c4 + 1] = v.y;
            s[row * 67 + c4 + 2] = v.z;
            s[row * 67 + c4 + 3] = v.w;
        }
        __syncthreads();

        const int oc = tid >> 2;
        const int ch = (tid & 3) * 8;
        uint32_t u[4];
        #pragma unroll
        for (int j = 0; j < 4; j++) {
            __half2 h = __floats2half2_rn(s[(ch + 2 * j) * 67 + oc],
                                          s[(ch + 2 * j + 1) * 67 + oc]);
            u[j] = *reinterpret_cast<uint32_t*>(&h);
        }
        *reinterpret_cast<uint4*>(o + (long long)(c0 + oc) * ldo + r0 + ch) =
            make_uint4(u[0], u[1], u[2], u[3]);
    } else {
        const size_t row = blockIdx.x - 6144;
        float* rs = s;
        float* rq = s + 8;
        const float4 v = reinterpret_cast<const float4*>(x + row * D_MODEL)[tid];
        float sm  = v.x + v.y + v.z + v.w;
        float sq  = v.x * v.x + v.y * v.y + v.z * v.z + v.w * v.w;
        #pragma unroll
        for (int o = 16; o; o >>= 1) {
            sm += __shfl_xor_sync(0xffffffffu, sm, o);
            sq += __shfl_xor_sync(0xffffffffu, sq, o);
        }
        if ((tid & 31) == 0) { rs[tid >> 5] = sm; rq[tid >> 5] = sq; }
        __syncthreads();
        float st = 0.0f, qt = 0.0f;
        #pragma unroll
        for (int i = 0; i < 8; i++) { st += rs[i]; qt += rq[i]; }
        const float mean = st * (1.0f / D_MODEL);
        const float var  = qt * (1.0f / D_MODEL) - mean * mean;
        const float rstd = rsqrtf(var + 1e-5f);

        const float4 gv = reinterpret_cast<const float4*>(g1)[tid];
        const float4 bv = reinterpret_cast<const float4*>(b1)[tid];
        const float o0 = (v.x - mean) * rstd * gv.x + bv.x;
        const float o1 = (v.y - mean) * rstd * gv.y + bv.y;
        const float o2 = (v.z - mean) * rstd * gv.z + bv.z;
        const float o3 = (v.w - mean) * rstd * gv.w + bv.w;
        __half2* op = reinterpret_cast<__half2*>(h16 + row * D_MODEL);
        op[2 * tid]     = __floats2half2_rn(o0, o1);
        op[2 * tid + 1] = __floats2half2_rn(o2, o3);
    }
}

// -------- LayerNorm -> fp16 (no out rewrite; fc2 bias folded into GEMM) ----
__global__ __launch_bounds__(256)
void ln_kernel(const float* __restrict__ x, const float* __restrict__ g,
               const float* __restrict__ b, __half* __restrict__ out)
{
    const size_t row = blockIdx.x;
    const float4 v = reinterpret_cast<const float4*>(x + row * D_MODEL)[threadIdx.x];
    float s  = v.x + v.y + v.z + v.w;
    float sq = v.x * v.x + v.y * v.y + v.z * v.z + v.w * v.w;

    __shared__ float rs[8], rq[8];
    #pragma unroll
    for (int o = 16; o; o >>= 1) {
        s  += __shfl_xor_sync(0xffffffffu, s, o);
        sq += __shfl_xor_sync(0xffffffffu, sq, o);
    }
    if ((threadIdx.x & 31) == 0) { rs[threadIdx.x >> 5] = s; rq[threadIdx.x >> 5] = sq; }
    __syncthreads();
    float st = 0.0f, qt = 0.0f;
    #pragma unroll
    for (int i = 0; i < 8; i++) { st += rs[i]; qt += rq[i]; }
    const float mean = st * (1.0f / D_MODEL);
    const float var  = qt * (1.0f / D_MODEL) - mean * mean;
    const float rstd = rsqrtf(var + 1e-5f);

    const float4 gv = reinterpret_cast<const float4*>(g)[threadIdx.x];
    const float4 bv = reinterpret_cast<const float4*>(b)[threadIdx.x];
    const float o0 = (v.x - mean) * rstd * gv.x + bv.x;
    const float o1 = (v.y - mean) * rstd * gv.y + bv.y;
    const float o2 = (v.z - mean) * rstd * gv.z + bv.z;
    const float o3 = (v.w - mean) * rstd * gv.w + bv.w;
    __half2* op = reinterpret_cast<__half2*>(out + row * D_MODEL);
    op[2 * threadIdx.x]     = __floats2half2_rn(o0, o1);
    op[2 * threadIdx.x + 1] = __floats2half2_rn(o2, o3);
}

// ---------------------------------------------------------------------------
extern "C" void kernel_launch(void* const* d_in, const int* in_sizes, int n_in,
                              void* d_out, int out_size)
{
    const float* x      = (const float*)d_in[0];
    const float* w_attn = (const float*)d_in[1];
    const float* b_attn = (const float*)d_in[2];
    const float* w_proj = (const float*)d_in[3];
    const float* b_proj = (const float*)d_in[4];
    const float* ln1_g  = (const float*)d_in[5];
    const float* ln1_b  = (const float*)d_in[6];
    const float* ln2_g  = (const float*)d_in[7];
    const float* ln2_b  = (const float*)d_in[8];
    const float* w_fc   = (const float*)d_in[9];
    const float* b_fc   = (const float*)d_in[10];
    const float* w_fc2  = (const float*)d_in[11];
    const float* b_fc2  = (const float*)d_in[12];
    float* out = (float*)d_out;

    __half *h16, *w16, *qkv16, *p16, *y16, *mlp16;
    float  *rsum;
    cudaGetSymbolAddress((void**)&h16,   g_h16);
    cudaGetSymbolAddress((void**)&w16,   g_w16);
    cudaGetSymbolAddress((void**)&qkv16, g_qkv16);
    cudaGetSymbolAddress((void**)&p16,   g_p16);
    cudaGetSymbolAddress((void**)&y16,   g_y16);
    cudaGetSymbolAddress((void**)&mlp16, g_mlp16);
    cudaGetSymbolAddress((void**)&rsum,  g_rowsum);

    const int SM_NT  = 3 * (128 * 144 + 128 * 144);   // 110592
    const int SM_TRB = 3 * (128 * 144 + 64 * 272);    // 107520
    cudaFuncSetAttribute(hgemm<0,1,1,0>, cudaFuncAttributeMaxDynamicSharedMemorySize, SM_NT);
    cudaFuncSetAttribute(hgemm<1,5,1,0>, cudaFuncAttributeMaxDynamicSharedMemorySize, SM_NT);
    cudaFuncSetAttribute(hgemm<2,6,1,1>, cudaFuncAttributeMaxDynamicSharedMemorySize, SM_TRB);
    cudaFuncSetAttribute(hgemm<0,2,0,0>, cudaFuncAttributeMaxDynamicSharedMemorySize, SM_NT);
    cudaFuncSetAttribute(hgemm<0,3,1,0>, cudaFuncAttributeMaxDynamicSharedMemorySize, SM_NT);
    cudaFuncSetAttribute(hgemm<0,7,0,0>, cudaFuncAttributeMaxDynamicSharedMemorySize, SM_NT);

    const long long sQ = (long long)T_SEQ * 3 * D_MODEL;
    const long long sS = (long long)T_SEQ * T_SEQ;
    const long long sY = (long long)T_SEQ * D_MODEL;

    // 0+1) weight transposes, LN1, rowsum zero-init — ONE launch
    head_kernel<<<6144 + ROWS + 8, 256>>>(w_attn, w_proj, w_fc, w_fc2, w16,
                                          x, ln1_g, ln1_b, h16, rsum);

    // 2) qkv = h @ w_attn + b_attn  (fp16 out)
    hgemm<0,1,1,0><<<dim3(24, 64, 1), 256, SM_NT>>>(
        h16, w16, b_attn, nullptr, qkv16, 1024, 1024, 1024, 3072, 0, 0, 0);

    // 3) expL = exp(q @ k^T / 8), causal-masked, rowsums accumulated
    hgemm<1,5,1,0><<<dim3(136, 1, N_BATCH), 256, SM_NT>>>(
        qkv16, qkv16 + D_MODEL, nullptr, rsum, p16,
        1024, 3072, 3072, 2048, sQ, sQ, sS);

    // 4) y = (expL @ v) / rowsum  (TRANS-B; K truncated at diagonal)
    hgemm<2,6,1,1><<<dim3(8, 16, N_BATCH), 256, SM_TRB>>>(
        p16, qkv16 + 2 * D_MODEL, rsum, nullptr, y16,
        2048, 2048, 3072, 1024, sS, sQ, sY);

    // 5) out = x + y @ w_proj + b_proj  (fp32 out, full-K — R15 proven)
    hgemm<0,2,0,0><<<dim3(8, 64, 1), 256, SM_NT>>>(
        y16, w16 + OFF_PROJ, b_proj, x, out, 1024, 1024, 1024, 1024, 0, 0, 0);

    // 6) LN2 -> h16 (no out rewrite; fc2 bias now added inside fc2)
    ln_kernel<<<ROWS, 256>>>(out, ln2_g, ln2_b, h16);

    // 7) mlp = gelu(h @ w_fc + b_fc)  (fp16 out)
    hgemm<0,3,1,0><<<dim3(32, 64, 1), 256, SM_NT>>>(
        h16, w16 + OFF_FC, b_fc, nullptr, mlp16, 1024, 1024, 1024, 4096, 0, 0, 0);

    // 8) out += mlp @ w_fc2 (+ b_fc2 on z==0), split-K=4 red.add
    hgemm<0,7,0,0><<<dim3(8, 64, 4), 256, SM_NT>>>(
        mlp16, w16 + OFF_FC2, b_fc2, nullptr, out,
        1024, 4096, 4096, 1024, 1024, 1024, 0);
}